// round 7
// baseline (speedup 1.0000x reference)
#include <cuda_runtime.h>
#include <cstdint>

// out = tanh(in @ Lr^T + br) + in @ Ld^T + bd + in
// Edge-flow scatter:
//   per edge k: vr = wr_k*in[ej]; r[ej]+=vr; r[ei]-=vr;
//               vd = wd_k*in[ei]; d[ei]+=vd; d[ej]-=vd;
// Cluster-of-2 per batch. Nodes are owned: rank0 owns [0,104), rank1 [104,207).
// Every atomic add is routed directly to the OWNER's smem via
// red.relaxed.cluster.shared::cluster (mapa). After one cluster barrier each
// CTA's smem holds final sums for its owned nodes -> purely local epilogue.

#define NN 207
#define NE 1722
#define BATCH 64
#define THREADS 512
#define SPLIT 864               // rank0 edges [0,864), rank1 [864,1722)
#define N0_HALF 104             // ownership split

__device__ __forceinline__ uint32_t smem_u32(const void* p) {
    uint32_t a;
    asm("{ .reg .u64 t; cvta.to.shared.u64 t, %1; cvt.u32.u64 %0, t; }"
        : "=r"(a) : "l"(p));
    return a;
}

__device__ __forceinline__ uint32_t mapa_rank(uint32_t laddr, uint32_t rank) {
    uint32_t pa;
    asm("mapa.shared::cluster.u32 %0, %1, %2;" : "=r"(pa) : "r"(laddr), "r"(rank));
    return pa;
}

__device__ __forceinline__ void red_cluster_f32(uint32_t addr, float v) {
    asm volatile("red.relaxed.cluster.shared::cluster.add.f32 [%0], %1;"
                 :: "r"(addr), "f"(v) : "memory");
}

__device__ __forceinline__ float tanh_approx(float x) {
    float y;
    asm("tanh.approx.f32 %0, %1;" : "=f"(y) : "f"(x));
    return y;
}

__global__ __launch_bounds__(THREADS) __cluster_dims__(2, 1, 1)
void rd_cluster_k(const float* __restrict__ in,
                  const float* __restrict__ wr,
                  const float* __restrict__ wd,
                  const float* __restrict__ br,
                  const float* __restrict__ bd,
                  const int*   __restrict__ ei,
                  const int*   __restrict__ ej,
                  float* __restrict__ out) {
    __shared__ float  s_in[NN];
    __shared__ float2 s_rd[NN];          // (reaction, diffusion); owned half valid

    const int tid   = threadIdx.x;
    const int batch = blockIdx.x >> 1;
    uint32_t rank;
    asm("mov.u32 %0, %%cluster_ctarank;" : "=r"(rank));
    const uint32_t rd_base = smem_u32(s_rd);

    // ---- prefetch my 2 edges (4 x LDG.64, high MLP) ----
    const int base  = rank ? SPLIT : 0;
    const int cnt   = rank ? (NE - SPLIT) : SPLIT;   // 864 / 858
    const int pairs = cnt >> 1;                       // 432 / 429 (< THREADS)
    int2 ii, jj; float2 wrr, wdd;
    const bool has_edges = (tid < pairs);
    if (has_edges) {
        const int k = base + 2 * tid;
        ii  = *reinterpret_cast<const int2*>(&ei[k]);
        jj  = *reinterpret_cast<const int2*>(&ej[k]);
        wrr = *reinterpret_cast<const float2*>(&wr[k]);
        wdd = *reinterpret_cast<const float2*>(&wd[k]);
    }

    // ---- prefetch epilogue bias (latency hides under scatter) ----
    const int n_base = rank ? N0_HALF : 0;
    const int n_cnt  = rank ? (NN - N0_HALF) : N0_HALF;
    float brn = 0.0f, bdn = 0.0f;
    const int n_out = n_base + tid;
    if (tid < n_cnt) {
        brn = br[n_out];
        bdn = bd[n_out];
    }

    // ---- load input row + zero accumulators ----
    if (tid < NN) {
        s_in[tid] = in[batch * NN + tid];
        s_rd[tid] = make_float2(0.0f, 0.0f);
    }

    // barrier #1: zeros + s_in visible cluster-wide before any red arrives
    asm volatile("barrier.cluster.arrive.aligned;" ::: "memory");
    asm volatile("barrier.cluster.wait.aligned;"   ::: "memory");

    // ---- scatter: owner-routed cluster reds ----
    if (has_edges) {
        #pragma unroll
        for (int e = 0; e < 2; e++) {
            const int i = e ? ii.y : ii.x;
            const int j = e ? jj.y : jj.x;
            const float w_r = e ? wrr.y : wrr.x;
            const float w_d = e ? wdd.y : wdd.x;
            const float vr = w_r * s_in[j];
            const float vd = w_d * s_in[i];
            const uint32_t pa_j = mapa_rank(rd_base + (uint32_t)j * 8u,
                                            (uint32_t)(j >= N0_HALF));
            const uint32_t pa_i = mapa_rank(rd_base + (uint32_t)i * 8u,
                                            (uint32_t)(i >= N0_HALF));
            red_cluster_f32(pa_j,      vr);   // r[j] += vr
            red_cluster_f32(pa_i,     -vr);   // r[i] -= vr
            red_cluster_f32(pa_i + 4,  vd);   // d[i] += vd
            red_cluster_f32(pa_j + 4, -vd);   // d[j] -= vd
        }
    }

    // barrier #2: all reds (local+remote) complete & visible
    asm volatile("barrier.cluster.arrive.aligned;" ::: "memory");
    asm volatile("barrier.cluster.wait.aligned;"   ::: "memory");

    // ---- epilogue: purely local ----
    if (tid < n_cnt) {
        const float2 acc = s_rd[n_out];
        out[batch * NN + n_out] =
            tanh_approx(acc.x + brn) + acc.y + bdn + s_in[n_out];
    }
    // no trailing barrier needed: no remote writes can target this CTA's smem
    // after barrier #2, and the epilogue reads only local smem.
}

extern "C" void kernel_launch(void* const* d_in, const int* in_sizes, int n_in,
                              void* d_out, int out_size) {
    const float* in_ = (const float*)d_in[0];
    const float* wr  = (const float*)d_in[1];
    const float* wd  = (const float*)d_in[2];
    const float* br  = (const float*)d_in[3];
    const float* bd  = (const float*)d_in[4];
    const int*   ei  = (const int*)d_in[5];
    const int*   ej  = (const int*)d_in[6];
    float* out = (float*)d_out;

    rd_cluster_k<<<BATCH * 2, THREADS>>>(in_, wr, wd, br, bd, ei, ej, out);
}

// round 8
// speedup vs baseline: 3.2122x; 3.2122x over previous
#include <cuda_runtime.h>
#include <cstdint>

// out = tanh(in @ Lr^T + br) + in @ Ld^T + bd + in
// Edge-flow scatter:
//   per edge k: vr = wr_k*in[ej]; r[ej]+=vr; r[ei]-=vr;
//               vd = wd_k*in[ei]; d[ei]+=vd; d[ej]-=vd;
//
// Target-split, fully independent CTAs: CTA = (batch, node-half).
// Each CTA reads ALL edges (L2-broadcast) but applies only the atomic updates
// whose target node lies in its owned half -> same smem-atomic lane count as
// an edge-split (≈2 lanes/edge) with ZERO cross-CTA synchronization.

#define NN 207
#define NE 1722
#define NPAIRS (NE / 2)      // 861
#define BATCH 64
#define THREADS 512
#define HALF0 104            // half 0 owns nodes [0,104), half 1 owns [104,207)

__device__ __forceinline__ float tanh_approx(float x) {
    float y;
    asm("tanh.approx.f32 %0, %1;" : "=f"(y) : "f"(x));
    return y;
}

__global__ __launch_bounds__(THREADS)
void rd_k(const float* __restrict__ in,
          const float* __restrict__ wr,
          const float* __restrict__ wd,
          const float* __restrict__ br,
          const float* __restrict__ bd,
          const int*   __restrict__ ei,
          const int*   __restrict__ ej,
          float* __restrict__ out) {
    __shared__ float s_in[NN];
    __shared__ float s_r[NN];
    __shared__ float s_d[NN];

    const int tid   = threadIdx.x;
    const int batch = blockIdx.x >> 1;
    const int half  = blockIdx.x & 1;
    const int n_lo  = half ? HALF0 : 0;
    const int n_hi  = half ? NN : HALF0;

    // ---- prefetch edge pairs (high-MLP LDG.64 burst) ----
    // pair A: tid (all threads, 861 > 512), pair B: tid+512 (tid < 349)
    const int kA = 2 * tid;
    int2 iA = *reinterpret_cast<const int2*>(&ei[kA]);
    int2 jA = *reinterpret_cast<const int2*>(&ej[kA]);
    float2 rA = *reinterpret_cast<const float2*>(&wr[kA]);
    float2 dA = *reinterpret_cast<const float2*>(&wd[kA]);
    const bool hasB = (tid + THREADS) < NPAIRS;
    int2 iB; int2 jB; float2 rB; float2 dB;
    if (hasB) {
        const int kB = 2 * (tid + THREADS);
        iB = *reinterpret_cast<const int2*>(&ei[kB]);
        jB = *reinterpret_cast<const int2*>(&ej[kB]);
        rB = *reinterpret_cast<const float2*>(&wr[kB]);
        dB = *reinterpret_cast<const float2*>(&wd[kB]);
    }

    // ---- prefetch epilogue biases (latency hides under scatter) ----
    const int n_out = n_lo + tid;
    float brn = 0.0f, bdn = 0.0f;
    if (n_out < n_hi) {
        brn = br[n_out];
        bdn = bd[n_out];
    }

    // ---- load input row + zero accumulators ----
    if (tid < NN) {
        s_in[tid] = in[batch * NN + tid];
        s_r[tid]  = 0.0f;
        s_d[tid]  = 0.0f;
    }
    __syncthreads();

    // ---- scatter: only updates targeting my node half ----
    #define PROCESS(i_, j_, wr_, wd_)                               \
    do {                                                            \
        const int i = (i_), j = (j_);                               \
        const float vr = (wr_) * s_in[j];                           \
        const float vd = (wd_) * s_in[i];                           \
        if ((j >= HALF0) == half) {                                 \
            atomicAdd(&s_r[j],  vr);                                \
            atomicAdd(&s_d[j], -vd);                                \
        }                                                           \
        if ((i >= HALF0) == half) {                                 \
            atomicAdd(&s_r[i], -vr);                                \
            atomicAdd(&s_d[i],  vd);                                \
        }                                                           \
    } while (0)

    PROCESS(iA.x, jA.x, rA.x, dA.x);
    PROCESS(iA.y, jA.y, rA.y, dA.y);
    if (hasB) {
        PROCESS(iB.x, jB.x, rB.x, dB.x);
        PROCESS(iB.y, jB.y, rB.y, dB.y);
    }
    #undef PROCESS
    __syncthreads();

    // ---- epilogue: purely local ----
    if (n_out < n_hi) {
        out[batch * NN + n_out] =
            tanh_approx(s_r[n_out] + brn) + s_d[n_out] + bdn + s_in[n_out];
    }
}

extern "C" void kernel_launch(void* const* d_in, const int* in_sizes, int n_in,
                              void* d_out, int out_size) {
    const float* in_ = (const float*)d_in[0];
    const float* wr  = (const float*)d_in[1];
    const float* wd  = (const float*)d_in[2];
    const float* br  = (const float*)d_in[3];
    const float* bd  = (const float*)d_in[4];
    const int*   ei  = (const int*)d_in[5];
    const int*   ej  = (const int*)d_in[6];
    float* out = (float*)d_out;

    rd_k<<<BATCH * 2, THREADS>>>(in_, wr, wd, br, bd, ei, ej, out);
}